// round 4
// baseline (speedup 1.0000x reference)
#include <cuda_runtime.h>

#define N_NODES 100000
#define F_IN    1433
#define H1      32
#define H2      16
#define NEDGE   3200000

// ---------------- scratch (no allocations allowed) ----------------
__device__ int    g_is64;                      // 1 if edge_index arrived as int64
__device__ int    g_src[NEDGE];
__device__ int    g_dst[NEDGE];
__device__ int    g_deg[N_NODES];
__device__ float  g_isq[N_NODES];
__device__ float4 g_h1s [N_NODES * H1 / 4];    // isq-prescaled h1  (16B aligned)
__device__ float4 g_agg1[N_NODES * H1 / 4];    // accumulator (init = h1s -> self loop)
__device__ float4 g_h2s [N_NODES * H2 / 4];
__device__ float4 g_agg2[N_NODES * H2 / 4];

// ---------------- K0: degree init (self loop) + flag init ----------------
__global__ void k_deg_init() {
    int i = blockIdx.x * blockDim.x + threadIdx.x;
    if (i == 0) g_is64 = 1;
    if (i < N_NODES) g_deg[i] = 1;
}

// ---------------- K0b: detect edge_index dtype -----------------------------
// Reads ONLY the first 2*NEDGE int32 words (in-bounds for both layouts).
// int64 layout: words 2i+1 are high words of src values (< 100000) -> all 0.
// int32 layout: words 2i+1 are random node indices -> many nonzero.
__global__ void k_detect(const int* __restrict__ ei32) {
    int i = blockIdx.x * blockDim.x + threadIdx.x;
    if (i < NEDGE && ei32[2 * i + 1] != 0) g_is64 = 0;   // benign race: all write 0
}

// ---------------- K1: edge convert + degree ----------------
__global__ void k_edge(const int* __restrict__ ei32) {
    int e = blockIdx.x * blockDim.x + threadIdx.x;
    if (e < NEDGE) {
        int s, d;
        if (g_is64) {                 // int64 little-endian: take low words
            s = ei32[2 * e];
            d = ei32[2 * NEDGE + 2 * e];
        } else {                      // int32
            s = ei32[e];
            d = ei32[NEDGE + e];
        }
        g_src[e] = s;
        g_dst[e] = d;
        atomicAdd(&g_deg[d], 1);
    }
}

// ---------------- K2: deg^-1/2 ----------------
__global__ void k_isq() {
    int i = blockIdx.x * blockDim.x + threadIdx.x;
    if (i < N_NODES) g_isq[i] = rsqrtf((float)g_deg[i]);
}

// ---------------- K3: h1s = isq * (x @ W1) ; agg1 = h1s ----------------
// Block: 256 threads, 256 rows. W1 (padded to 1440 rows) fully in smem.
#define KC 16
#define RB 256
#define W_PAD_ROWS 1440
#define SMEM1_FLOATS (W_PAD_ROWS * H1 + RB * 17)

__global__ void __launch_bounds__(256, 1)
k_gemm1(const float* __restrict__ x, const float* __restrict__ W1) {
    extern __shared__ float sm[];
    float* Ws = sm;                       // [1440][32]
    float* xs = sm + W_PAD_ROWS * H1;     // [256][17]  (pad 17 avoids bank conflicts)

    const int tid = threadIdx.x;
    for (int idx = tid; idx < W_PAD_ROWS * H1; idx += 256)
        Ws[idx] = (idx < F_IN * H1) ? W1[idx] : 0.0f;

    const int jg   = tid & 7;     // column group: cols 4*jg .. 4*jg+3
    const int rr   = tid >> 3;    // 0..31
    const int row0 = blockIdx.x * RB;

    float acc[8][4];
#pragma unroll
    for (int i = 0; i < 8; i++) { acc[i][0]=0.f; acc[i][1]=0.f; acc[i][2]=0.f; acc[i][3]=0.f; }

    const int kk_ld = tid & 15;
    const int rb_ld = tid >> 4;   // 0..15

    for (int kt = 0; kt < (F_IN + KC - 1) / KC; kt++) {
        const int k0 = kt * KC;
        __syncthreads();
        {
            const int k = k0 + kk_ld;
#pragma unroll
            for (int t = 0; t < 16; t++) {
                const int r = rb_ld + t * 16;
                const int row = row0 + r;
                float v = 0.0f;
                if (k < F_IN && row < N_NODES) v = x[(size_t)row * F_IN + k];
                xs[r * 17 + kk_ld] = v;
            }
        }
        __syncthreads();
#pragma unroll
        for (int kk = 0; kk < KC; kk++) {
            const int k = k0 + kk;
            const float4 w = *(const float4*)&Ws[k * H1 + jg * 4];
#pragma unroll
            for (int i = 0; i < 8; i++) {
                const float xv = xs[(rr + 32 * i) * 17 + kk];
                acc[i][0] += xv * w.x;
                acc[i][1] += xv * w.y;
                acc[i][2] += xv * w.z;
                acc[i][3] += xv * w.w;
            }
        }
    }
#pragma unroll
    for (int i = 0; i < 8; i++) {
        const int row = row0 + rr + 32 * i;
        if (row < N_NODES) {
            const float q = g_isq[row];
            float4 o = make_float4(acc[i][0]*q, acc[i][1]*q, acc[i][2]*q, acc[i][3]*q);
            g_h1s [row * (H1/4) + jg] = o;
            g_agg1[row * (H1/4) + jg] = o;   // self-loop term
        }
    }
}

// ---------------- vectorized global float4 reduction ----------------
__device__ __forceinline__ void red_add_v4(float4* p, float4 v) {
    asm volatile("red.global.add.v4.f32 [%0], {%1,%2,%3,%4};"
                 :: "l"(p), "f"(v.x), "f"(v.y), "f"(v.z), "f"(v.w) : "memory");
}

// ---------------- K4: scatter layer 1 (8 threads / edge) ----------------
__global__ void k_scatter1() {
    const int tid = blockIdx.x * blockDim.x + threadIdx.x;
    const int e = tid >> 3;
    const int q = tid & 7;
    if (e < NEDGE) {
        const int s = g_src[e];
        const int d = g_dst[e];
        const float4 v = g_h1s[s * (H1/4) + q];
        red_add_v4(&g_agg1[d * (H1/4) + q], v);
    }
}

// ---------------- K5: a1 = relu(isq*agg1 + b1); h2s = isq*(a1@W2); agg2 = h2s ----
__global__ void k_layer2(const float* __restrict__ W2, const float* __restrict__ b1) {
    __shared__ float W2s[H1 * H2];
    __shared__ float b1s[H1];
    for (int i = threadIdx.x; i < H1 * H2; i += blockDim.x) W2s[i] = W2[i];
    if (threadIdx.x < H1) b1s[threadIdx.x] = b1[threadIdx.x];
    __syncthreads();

    const int node = blockIdx.x * blockDim.x + threadIdx.x;
    if (node >= N_NODES) return;
    const float q = g_isq[node];

    float a[H1];
#pragma unroll
    for (int k4 = 0; k4 < H1 / 4; k4++) {
        const float4 v = g_agg1[node * (H1/4) + k4];
        a[k4*4+0] = fmaxf(v.x * q + b1s[k4*4+0], 0.0f);
        a[k4*4+1] = fmaxf(v.y * q + b1s[k4*4+1], 0.0f);
        a[k4*4+2] = fmaxf(v.z * q + b1s[k4*4+2], 0.0f);
        a[k4*4+3] = fmaxf(v.w * q + b1s[k4*4+3], 0.0f);
    }
    float acc[H2];
#pragma unroll
    for (int j = 0; j < H2; j++) acc[j] = 0.0f;
#pragma unroll
    for (int k = 0; k < H1; k++) {
        const float ak = a[k];
#pragma unroll
        for (int j4 = 0; j4 < H2 / 4; j4++) {
            const float4 w = *(const float4*)&W2s[k * H2 + j4 * 4];
            acc[j4*4+0] += ak * w.x;
            acc[j4*4+1] += ak * w.y;
            acc[j4*4+2] += ak * w.z;
            acc[j4*4+3] += ak * w.w;
        }
    }
#pragma unroll
    for (int j4 = 0; j4 < H2 / 4; j4++) {
        float4 o = make_float4(acc[j4*4+0]*q, acc[j4*4+1]*q, acc[j4*4+2]*q, acc[j4*4+3]*q);
        g_h2s [node * (H2/4) + j4] = o;
        g_agg2[node * (H2/4) + j4] = o;   // self-loop term
    }
}

// ---------------- K6: scatter layer 2 (4 threads / edge) ----------------
__global__ void k_scatter2() {
    const int tid = blockIdx.x * blockDim.x + threadIdx.x;
    const int e = tid >> 2;
    const int q = tid & 3;
    if (e < NEDGE) {
        const int s = g_src[e];
        const int d = g_dst[e];
        const float4 v = g_h2s[s * (H2/4) + q];
        red_add_v4(&g_agg2[d * (H2/4) + q], v);
    }
}

// ---------------- K7: out = log_softmax(relu(isq*agg2 + b2) @ Wl + bl) ----------
#define SMEM7_FLOATS (H2 * F_IN + F_IN + 16 + 32)
__global__ void __launch_bounds__(256, 2)
k_final(const float* __restrict__ Wl, const float* __restrict__ bl,
        const float* __restrict__ b2, float* __restrict__ out) {
    extern __shared__ float sm[];
    float* Wls = sm;                    // [16][1433]
    float* bls = sm + H2 * F_IN;        // [1433]
    float* a2s = bls + F_IN;            // [16]
    float* red = a2s + 16;              // [16] partials

    for (int i = threadIdx.x; i < H2 * F_IN; i += 256) Wls[i] = Wl[i];
    for (int i = threadIdx.x; i < F_IN; i += 256)      bls[i] = bl[i];
    __syncthreads();

    const int lane = threadIdx.x & 31;
    const int warp = threadIdx.x >> 5;
    const float* agg2f = (const float*)g_agg2;

    for (int node = blockIdx.x; node < N_NODES; node += gridDim.x) {
        if (threadIdx.x < H2) {
            const float q = g_isq[node];
            a2s[threadIdx.x] = fmaxf(q * agg2f[node * H2 + threadIdx.x] + b2[threadIdx.x], 0.0f);
        }
        __syncthreads();

        float a2[H2];
#pragma unroll
        for (int k = 0; k < H2; k++) a2[k] = a2s[k];

        float z[6];
        float mx = -1e30f;
#pragma unroll
        for (int t = 0; t < 6; t++) {
            const int c = threadIdx.x + t * 256;
            float zz = -1e30f;
            if (c < F_IN) {
                zz = bls[c];
#pragma unroll
                for (int k = 0; k < H2; k++) zz += a2[k] * Wls[k * F_IN + c];
            }
            z[t] = zz;
            mx = fmaxf(mx, zz);
        }
#pragma unroll
        for (int o = 16; o > 0; o >>= 1) mx = fmaxf(mx, __shfl_xor_sync(0xffffffffu, mx, o));
        if (lane == 0) red[warp] = mx;
        __syncthreads();
        float bm = red[0];
#pragma unroll
        for (int w = 1; w < 8; w++) bm = fmaxf(bm, red[w]);

        float se = 0.0f;
#pragma unroll
        for (int t = 0; t < 6; t++) {
            const int c = threadIdx.x + t * 256;
            if (c < F_IN) se += __expf(z[t] - bm);
        }
#pragma unroll
        for (int o = 16; o > 0; o >>= 1) se += __shfl_xor_sync(0xffffffffu, se, o);
        if (lane == 0) red[8 + warp] = se;
        __syncthreads();
        float s = 0.0f;
#pragma unroll
        for (int w = 0; w < 8; w++) s += red[8 + w];
        const float lse = bm + __logf(s);

#pragma unroll
        for (int t = 0; t < 6; t++) {
            const int c = threadIdx.x + t * 256;
            if (c < F_IN) out[(size_t)node * F_IN + c] = z[t] - lse;
        }
        __syncthreads();   // protect a2s / red for next node
    }
}

// ---------------- launcher ----------------
extern "C" void kernel_launch(void* const* d_in, const int* in_sizes, int n_in,
                              void* d_out, int out_size) {
    const float* x   = (const float*)d_in[0];
    const float* W1  = (const float*)d_in[1];
    const float* b1  = (const float*)d_in[2];
    const float* W2  = (const float*)d_in[3];
    const float* b2  = (const float*)d_in[4];
    const float* Wl  = (const float*)d_in[5];
    const float* bl  = (const float*)d_in[6];
    const int*   ei32 = (const int*)d_in[7];   // int32 OR int64 (auto-detected)
    float* out = (float*)d_out;
    (void)in_sizes; (void)n_in; (void)out_size;

    const int smem1 = SMEM1_FLOATS * (int)sizeof(float);   // ~201.7 KB
    const int smem7 = SMEM7_FLOATS * (int)sizeof(float);   // ~97.7 KB
    cudaFuncSetAttribute(k_gemm1, cudaFuncAttributeMaxDynamicSharedMemorySize, smem1);
    cudaFuncSetAttribute(k_final, cudaFuncAttributeMaxDynamicSharedMemorySize, smem7);

    k_deg_init<<<(N_NODES + 255) / 256, 256>>>();
    k_detect  <<<(NEDGE   + 255) / 256, 256>>>(ei32);
    k_edge    <<<(NEDGE   + 255) / 256, 256>>>(ei32);
    k_isq     <<<(N_NODES + 255) / 256, 256>>>();

    k_gemm1   <<<(N_NODES + RB - 1) / RB, 256, smem1>>>(x, W1);
    k_scatter1<<<(NEDGE * 8 + 255) / 256, 256>>>();
    k_layer2  <<<(N_NODES + 127) / 128, 128>>>(W2, b1);
    k_scatter2<<<(NEDGE * 4 + 255) / 256, 256>>>();
    k_final   <<<296, 256, smem7>>>(Wl, bl, b2, out);
}

// round 5
// speedup vs baseline: 1.1497x; 1.1497x over previous
#include <cuda_runtime.h>

#define N_NODES 100000
#define F_IN    1433
#define H1      32
#define H2      16
#define NEDGE   3200000

// ---------------- scratch (no allocations allowed) ----------------
__device__ int    g_is64;                      // 1 if edge_index arrived as int64
__device__ int    g_src[NEDGE];
__device__ int    g_dst[NEDGE];
__device__ int    g_deg[N_NODES];
__device__ float  g_isq[N_NODES];
__device__ float4 g_h1s [N_NODES * H1 / 4];    // isq-prescaled h1  (16B aligned)
__device__ float4 g_agg1[N_NODES * H1 / 4];    // accumulator (init = h1s -> self loop)
__device__ float4 g_h2s [N_NODES * H2 / 4];
__device__ float4 g_agg2[N_NODES * H2 / 4];

// ---------------- K0: degree init (self loop) + flag init ----------------
__global__ void k_deg_init() {
    int i = blockIdx.x * blockDim.x + threadIdx.x;
    if (i == 0) g_is64 = 1;
    if (i < N_NODES) g_deg[i] = 1;
}

// ---------------- K0b: detect edge_index dtype -----------------------------
// int64 layout: words 2i+1 are high words of src (< 100000) -> all 0.
// int32 layout: words 2i+1 are random node indices -> many nonzero.
__global__ void k_detect(const int* __restrict__ ei32) {
    int i = blockIdx.x * blockDim.x + threadIdx.x;
    if (i < NEDGE && ei32[2 * i + 1] != 0) g_is64 = 0;
}

// ---------------- K1: edge convert + degree ----------------
__global__ void k_edge(const int* __restrict__ ei32) {
    int e = blockIdx.x * blockDim.x + threadIdx.x;
    if (e < NEDGE) {
        int s, d;
        if (g_is64) {                 // int64 little-endian: take low words, 8B loads
            const int2* p = (const int2*)ei32;
            s = p[e].x;
            d = p[NEDGE + e].x;
        } else {
            s = ei32[e];
            d = ei32[NEDGE + e];
        }
        g_src[e] = s;
        g_dst[e] = d;
        atomicAdd(&g_deg[d], 1);
    }
}

// ---------------- K2: deg^-1/2 ----------------
__global__ void k_isq() {
    int i = blockIdx.x * blockDim.x + threadIdx.x;
    if (i < N_NODES) g_isq[i] = rsqrtf((float)g_deg[i]);
}

// ---------------- K3: h1s = isq * (x @ W1) ; agg1 = h1s ----------------
// 512 threads, 256 rows/block. W1 fully in smem (180 KB) + double-buffered x
// tiles (2 x 17.4 KB). Next tile is loaded into registers during compute of
// the current tile -> staging latency fully hidden behind the FFMA pipe.
#define KC 16
#define RB 256
#define NKT ((F_IN + KC - 1) / KC)          // 90
#define W_PAD_ROWS (NKT * KC)               // 1440
#define SMEM1_FLOATS (W_PAD_ROWS * H1 + 2 * RB * 17)

__global__ void __launch_bounds__(512, 1)
k_gemm1(const float* __restrict__ x, const float* __restrict__ W1) {
    extern __shared__ float sm[];
    float* Ws  = sm;                        // [1440][32]
    float* xs0 = sm + W_PAD_ROWS * H1;      // [256][17]
    float* xs1 = xs0 + RB * 17;             // [256][17]

    const int tid = threadIdx.x;
    for (int idx = tid; idx < W_PAD_ROWS * H1; idx += 512)
        Ws[idx] = (idx < F_IN * H1) ? W1[idx] : 0.0f;

    const int jg   = tid & 7;     // column group: cols 4*jg .. 4*jg+3
    const int rr   = tid >> 3;    // 0..63 -> rows rr + 64*i
    const int row0 = blockIdx.x * RB;

    const int kk_ld = tid & 15;
    const int rb_ld = tid >> 4;   // 0..31 -> rows rb_ld + 32*t

    float r[8];
    // prologue: load tile 0
    {
#pragma unroll
        for (int t = 0; t < 8; t++) {
            const int row = row0 + rb_ld + 32 * t;
            r[t] = (kk_ld < F_IN && row < N_NODES) ? x[(size_t)row * F_IN + kk_ld] : 0.0f;
        }
    }
    __syncthreads();   // Ws ready
#pragma unroll
    for (int t = 0; t < 8; t++) xs0[(rb_ld + 32 * t) * 17 + kk_ld] = r[t];
    __syncthreads();

    float acc[4][4];
#pragma unroll
    for (int i = 0; i < 4; i++) { acc[i][0]=0.f; acc[i][1]=0.f; acc[i][2]=0.f; acc[i][3]=0.f; }

    for (int kt = 0; kt < NKT; kt++) {
        const float* cur = (kt & 1) ? xs1 : xs0;
        float*       nxt = (kt & 1) ? xs0 : xs1;

        // issue next tile's loads (latency overlaps the compute below)
        if (kt + 1 < NKT) {
            const int k = (kt + 1) * KC + kk_ld;
#pragma unroll
            for (int t = 0; t < 8; t++) {
                const int row = row0 + rb_ld + 32 * t;
                r[t] = (k < F_IN && row < N_NODES) ? x[(size_t)row * F_IN + k] : 0.0f;
            }
        }

#pragma unroll
        for (int kk = 0; kk < KC; kk++) {
            const int k = kt * KC + kk;
            const float4 w = *(const float4*)&Ws[k * H1 + jg * 4];
#pragma unroll
            for (int i = 0; i < 4; i++) {
                const float xv = cur[(rr + 64 * i) * 17 + kk];
                acc[i][0] += xv * w.x;
                acc[i][1] += xv * w.y;
                acc[i][2] += xv * w.z;
                acc[i][3] += xv * w.w;
            }
        }
        __syncthreads();                     // everyone done reading nxt's old data
        if (kt + 1 < NKT) {
#pragma unroll
            for (int t = 0; t < 8; t++) nxt[(rb_ld + 32 * t) * 17 + kk_ld] = r[t];
        }
        __syncthreads();                     // nxt ready for next iteration
    }

#pragma unroll
    for (int i = 0; i < 4; i++) {
        const int row = row0 + rr + 64 * i;
        if (row < N_NODES) {
            const float q = g_isq[row];
            float4 o = make_float4(acc[i][0]*q, acc[i][1]*q, acc[i][2]*q, acc[i][3]*q);
            g_h1s [row * (H1/4) + jg] = o;
            g_agg1[row * (H1/4) + jg] = o;   // self-loop term
        }
    }
}

// ---------------- vectorized global float4 reduction ----------------
__device__ __forceinline__ void red_add_v4(float4* p, float4 v) {
    asm volatile("red.global.add.v4.f32 [%0], {%1,%2,%3,%4};"
                 :: "l"(p), "f"(v.x), "f"(v.y), "f"(v.z), "f"(v.w) : "memory");
}

// ---------------- K4: scatter layer 1 (8 threads / edge) ----------------
__global__ void k_scatter1() {
    const int tid = blockIdx.x * blockDim.x + threadIdx.x;
    const int e = tid >> 3;
    const int q = tid & 7;
    if (e < NEDGE) {
        const int s = g_src[e];
        const int d = g_dst[e];
        const float4 v = g_h1s[s * (H1/4) + q];
        red_add_v4(&g_agg1[d * (H1/4) + q], v);
    }
}

// ---------------- K5: a1 = relu(isq*agg1 + b1); h2s = isq*(a1@W2); agg2 = h2s ----
__global__ void k_layer2(const float* __restrict__ W2, const float* __restrict__ b1) {
    __shared__ float W2s[H1 * H2];
    __shared__ float b1s[H1];
    for (int i = threadIdx.x; i < H1 * H2; i += blockDim.x) W2s[i] = W2[i];
    if (threadIdx.x < H1) b1s[threadIdx.x] = b1[threadIdx.x];
    __syncthreads();

    const int node = blockIdx.x * blockDim.x + threadIdx.x;
    if (node >= N_NODES) return;
    const float q = g_isq[node];

    float a[H1];
#pragma unroll
    for (int k4 = 0; k4 < H1 / 4; k4++) {
        const float4 v = g_agg1[node * (H1/4) + k4];
        a[k4*4+0] = fmaxf(v.x * q + b1s[k4*4+0], 0.0f);
        a[k4*4+1] = fmaxf(v.y * q + b1s[k4*4+1], 0.0f);
        a[k4*4+2] = fmaxf(v.z * q + b1s[k4*4+2], 0.0f);
        a[k4*4+3] = fmaxf(v.w * q + b1s[k4*4+3], 0.0f);
    }
    float acc[H2];
#pragma unroll
    for (int j = 0; j < H2; j++) acc[j] = 0.0f;
#pragma unroll
    for (int k = 0; k < H1; k++) {
        const float ak = a[k];
#pragma unroll
        for (int j4 = 0; j4 < H2 / 4; j4++) {
            const float4 w = *(const float4*)&W2s[k * H2 + j4 * 4];
            acc[j4*4+0] += ak * w.x;
            acc[j4*4+1] += ak * w.y;
            acc[j4*4+2] += ak * w.z;
            acc[j4*4+3] += ak * w.w;
        }
    }
#pragma unroll
    for (int j4 = 0; j4 < H2 / 4; j4++) {
        float4 o = make_float4(acc[j4*4+0]*q, acc[j4*4+1]*q, acc[j4*4+2]*q, acc[j4*4+3]*q);
        g_h2s [node * (H2/4) + j4] = o;
        g_agg2[node * (H2/4) + j4] = o;   // self-loop term
    }
}

// ---------------- K6: scatter layer 2 (4 threads / edge) ----------------
__global__ void k_scatter2() {
    const int tid = blockIdx.x * blockDim.x + threadIdx.x;
    const int e = tid >> 2;
    const int q = tid & 3;
    if (e < NEDGE) {
        const int s = g_src[e];
        const int d = g_dst[e];
        const float4 v = g_h2s[s * (H2/4) + q];
        red_add_v4(&g_agg2[d * (H2/4) + q], v);
    }
}

// ---------------- K7: out = log_softmax(relu(isq*agg2 + b2) @ Wl + bl) ----------
// 2 nodes per block iteration: every Wls LDS now feeds 2 FFMA -> LDS and FFMA
// pipes co-limiting instead of LDS-bound at 2x.
#define SMEM7_FLOATS (H2 * F_IN + F_IN + H2 + 2 * H2 + 32)
__global__ void __launch_bounds__(256, 2)
k_final(const float* __restrict__ Wl, const float* __restrict__ bl,
        const float* __restrict__ b2, float* __restrict__ out) {
    extern __shared__ float sm[];
    float* Wls = sm;                    // [16][1433]
    float* bls = sm + H2 * F_IN;        // [1433]
    float* b2s = bls + F_IN;            // [16]
    float* a2s = b2s + H2;              // [2][16]
    float* red = a2s + 2 * H2;          // [32]: 16 max partials + 16 sum partials

    for (int i = threadIdx.x; i < H2 * F_IN; i += 256) Wls[i] = Wl[i];
    for (int i = threadIdx.x; i < F_IN; i += 256)      bls[i] = bl[i];
    if (threadIdx.x < H2)                              b2s[threadIdx.x] = b2[threadIdx.x];
    __syncthreads();

    const int lane = threadIdx.x & 31;
    const int warp = threadIdx.x >> 5;
    const float* agg2f = (const float*)g_agg2;

    for (int n0 = blockIdx.x * 2; n0 < N_NODES; n0 += gridDim.x * 2) {
        // stage relu'd a2 for both nodes (threads 0..31: nn = tid>>4, k = tid&15)
        if (threadIdx.x < 2 * H2) {
            const int nn   = threadIdx.x >> 4;
            const int k    = threadIdx.x & 15;
            const int node = n0 + nn;
            const float q  = g_isq[node];
            a2s[threadIdx.x] = fmaxf(q * agg2f[node * H2 + k] + b2s[k], 0.0f);
        }
        __syncthreads();

        float a20[H2], a21[H2];
#pragma unroll
        for (int k = 0; k < H2; k++) { a20[k] = a2s[k]; a21[k] = a2s[H2 + k]; }

        float z0[6], z1[6];
        float mx0 = -1e30f, mx1 = -1e30f;
#pragma unroll
        for (int t = 0; t < 6; t++) {
            const int c = threadIdx.x + t * 256;
            float s0 = -1e30f, s1 = -1e30f;
            if (c < F_IN) {
                s0 = bls[c]; s1 = s0;
#pragma unroll
                for (int k = 0; k < H2; k++) {
                    const float w = Wls[k * F_IN + c];
                    s0 += a20[k] * w;
                    s1 += a21[k] * w;
                }
            }
            z0[t] = s0; z1[t] = s1;
            mx0 = fmaxf(mx0, s0); mx1 = fmaxf(mx1, s1);
        }
#pragma unroll
        for (int o = 16; o > 0; o >>= 1) {
            mx0 = fmaxf(mx0, __shfl_xor_sync(0xffffffffu, mx0, o));
            mx1 = fmaxf(mx1, __shfl_xor_sync(0xffffffffu, mx1, o));
        }
        if (lane == 0) { red[warp] = mx0; red[8 + warp] = mx1; }
        __syncthreads();
        float bm0 = red[0], bm1 = red[8];
#pragma unroll
        for (int w = 1; w < 8; w++) { bm0 = fmaxf(bm0, red[w]); bm1 = fmaxf(bm1, red[8 + w]); }

        float se0 = 0.0f, se1 = 0.0f;
#pragma unroll
        for (int t = 0; t < 6; t++) {
            const int c = threadIdx.x + t * 256;
            if (c < F_IN) {
                se0 += __expf(z0[t] - bm0);
                se1 += __expf(z1[t] - bm1);
            }
        }
#pragma unroll
        for (int o = 16; o > 0; o >>= 1) {
            se0 += __shfl_xor_sync(0xffffffffu, se0, o);
            se1 += __shfl_xor_sync(0xffffffffu, se1, o);
        }
        if (lane == 0) { red[16 + warp] = se0; red[24 + warp] = se1; }
        __syncthreads();
        float s0 = 0.0f, s1 = 0.0f;
#pragma unroll
        for (int w = 0; w < 8; w++) { s0 += red[16 + w]; s1 += red[24 + w]; }
        const float lse0 = bm0 + __logf(s0);
        const float lse1 = bm1 + __logf(s1);

#pragma unroll
        for (int t = 0; t < 6; t++) {
            const int c = threadIdx.x + t * 256;
            if (c < F_IN) {
                out[(size_t)n0 * F_IN + c]           = z0[t] - lse0;
                out[(size_t)(n0 + 1) * F_IN + c]     = z1[t] - lse1;
            }
        }
        __syncthreads();   // protect a2s / red for next iteration
    }
}

// ---------------- launcher ----------------
extern "C" void kernel_launch(void* const* d_in, const int* in_sizes, int n_in,
                              void* d_out, int out_size) {
    const float* x   = (const float*)d_in[0];
    const float* W1  = (const float*)d_in[1];
    const float* b1  = (const float*)d_in[2];
    const float* W2  = (const float*)d_in[3];
    const float* b2  = (const float*)d_in[4];
    const float* Wl  = (const float*)d_in[5];
    const float* bl  = (const float*)d_in[6];
    const int*   ei32 = (const int*)d_in[7];   // int32 OR int64 (auto-detected)
    float* out = (float*)d_out;
    (void)in_sizes; (void)n_in; (void)out_size;

    const int smem1 = SMEM1_FLOATS * (int)sizeof(float);   // ~219 KB
    const int smem7 = SMEM7_FLOATS * (int)sizeof(float);   // ~98 KB
    cudaFuncSetAttribute(k_gemm1, cudaFuncAttributeMaxDynamicSharedMemorySize, smem1);
    cudaFuncSetAttribute(k_final, cudaFuncAttributeMaxDynamicSharedMemorySize, smem7);

    k_deg_init<<<(N_NODES + 255) / 256, 256>>>();
    k_detect  <<<(NEDGE   + 255) / 256, 256>>>(ei32);
    k_edge    <<<(NEDGE   + 255) / 256, 256>>>(ei32);
    k_isq     <<<(N_NODES + 255) / 256, 256>>>();

    k_gemm1   <<<(N_NODES + RB - 1) / RB, 512, smem1>>>(x, W1);
    k_scatter1<<<(NEDGE * 8 + 255) / 256, 256>>>();
    k_layer2  <<<(N_NODES + 127) / 128, 128>>>(W2, b1);
    k_scatter2<<<(NEDGE * 4 + 255) / 256, 256>>>();
    k_final   <<<296, 256, smem7>>>(Wl, bl, b2, out);
}

// round 8
// speedup vs baseline: 1.3127x; 1.1418x over previous
#include <cuda_runtime.h>

#define N_NODES 100000
#define F_IN    1433
#define H1      32
#define H2      16
#define NEDGE   3200000

// ---------------- scratch (no allocations allowed) ----------------
__device__ int    g_is64;
__device__ int    g_src[NEDGE];
__device__ int    g_dst[NEDGE];
__device__ int    g_deg[N_NODES];
__device__ float  g_isq[N_NODES];
__device__ float4 g_h1s [N_NODES * H1 / 4];
__device__ float4 g_agg1[N_NODES * H1 / 4];
__device__ float4 g_h2s [N_NODES * H2 / 4];
__device__ float4 g_agg2[N_NODES * H2 / 4];

// ---------------- packed f32x2 helpers (FFMA2 via PTX) ----------------
__device__ __forceinline__ unsigned long long pk2(float lo, float hi) {
    unsigned long long r;
    asm("mov.b64 %0, {%1, %2};" : "=l"(r) : "f"(lo), "f"(hi));
    return r;
}
__device__ __forceinline__ void upk2(float& lo, float& hi, unsigned long long p) {
    asm("mov.b64 {%0, %1}, %2;" : "=f"(lo), "=f"(hi) : "l"(p));
}
__device__ __forceinline__ void fma2(unsigned long long& d, unsigned long long a,
                                     unsigned long long b) {
    asm("fma.rn.f32x2 %0, %1, %2, %0;" : "+l"(d) : "l"(a), "l"(b));
}

// ---------------- K0: degree init (self loop) + flag init ----------------
__global__ void k_deg_init() {
    int i = blockIdx.x * blockDim.x + threadIdx.x;
    if (i == 0) g_is64 = 1;
    if (i < N_NODES) g_deg[i] = 1;
}

// ---------------- K0b: detect edge_index dtype ----------------
__global__ void k_detect(const int* __restrict__ ei32) {
    int i = blockIdx.x * blockDim.x + threadIdx.x;
    if (i < NEDGE && ei32[2 * i + 1] != 0) g_is64 = 0;
}

// ---------------- K1: edge convert + degree ----------------
__global__ void k_edge(const int* __restrict__ ei32) {
    int e = blockIdx.x * blockDim.x + threadIdx.x;
    if (e < NEDGE) {
        int s, d;
        if (g_is64) {
            const int2* p = (const int2*)ei32;
            s = p[e].x;
            d = p[NEDGE + e].x;
        } else {
            s = ei32[e];
            d = ei32[NEDGE + e];
        }
        g_src[e] = s;
        g_dst[e] = d;
        atomicAdd(&g_deg[d], 1);
    }
}

// ---------------- K2: deg^-1/2 (launched AFTER gemm1; gemm1 reads g_deg) ----
__global__ void k_isq() {
    int i = blockIdx.x * blockDim.x + threadIdx.x;
    if (i < N_NODES) g_isq[i] = rsqrtf((float)g_deg[i]);
}

// ---------------- K3: h1s = isq * (x @ W1) ; agg1 = h1s  (FFMA2) ----------
// 512 threads, 768 rows/block. Streamed, double-buffered x (768x16) and W
// (16x32) tiles. Per thread: 6 rows x 8 cols = 24 f32x2 accumulators.
#define KC 16
#define RB 768
#define NKT ((F_IN + KC - 1) / KC)           // 90
#define XS_STRIDE 17
#define XS_FLOATS (RB * XS_STRIDE)           // 13056
#define WS_FLOATS (KC * H1)                  // 512
#define SMEM1_FLOATS (2 * XS_FLOATS + 2 * WS_FLOATS)   // 27136 fl = 106 KB

__global__ void __launch_bounds__(512, 1)
k_gemm1(const float* __restrict__ x, const float* __restrict__ W1) {
    extern __shared__ float sm[];
    float* xs0 = sm;
    float* xs1 = xs0 + XS_FLOATS;
    float* ws0 = xs1 + XS_FLOATS;
    float* ws1 = ws0 + WS_FLOATS;

    const int tid = threadIdx.x;
    const int cg  = tid >> 7;      // 0..3 -> cols 8*cg..8*cg+7
    const int rt  = tid & 127;     // rows rt + 128*i, i<6
    const int row0 = blockIdx.x * RB;

    const int kk_ld = tid & 15;
    const int rl    = tid >> 4;    // 0..31 -> rows rl + 32*t, t<24
    const int wk_ld = tid >> 5;    // 0..15 (k within tile)
    const int wj_ld = tid & 31;    // col

    float r[24];
    float wr;
    // prologue: tile 0 -> regs -> smem buffer 0
    {
#pragma unroll
        for (int t = 0; t < 24; t++) {
            const int row = row0 + rl + 32 * t;
            r[t] = (kk_ld < F_IN && row < N_NODES) ? x[(size_t)row * F_IN + kk_ld] : 0.0f;
        }
        wr = (wk_ld < F_IN) ? W1[wk_ld * H1 + wj_ld] : 0.0f;
    }
#pragma unroll
    for (int t = 0; t < 24; t++) xs0[(rl + 32 * t) * XS_STRIDE + kk_ld] = r[t];
    ws0[tid] = wr;
    __syncthreads();

    unsigned long long acc[6][4];
#pragma unroll
    for (int i = 0; i < 6; i++)
#pragma unroll
        for (int p = 0; p < 4; p++) acc[i][p] = 0ull;

    for (int kt = 0; kt < NKT; kt++) {
        const float* xsc = (kt & 1) ? xs1 : xs0;
        const float* wsc = (kt & 1) ? ws1 : ws0;
        float* xsn = (kt & 1) ? xs0 : xs1;
        float* wsn = (kt & 1) ? ws0 : ws1;

        if (kt + 1 < NKT) {
            const int k = (kt + 1) * KC + kk_ld;
#pragma unroll
            for (int t = 0; t < 24; t++) {
                const int row = row0 + rl + 32 * t;
                r[t] = (k < F_IN && row < N_NODES) ? x[(size_t)row * F_IN + k] : 0.0f;
            }
            const int kw = (kt + 1) * KC + wk_ld;
            wr = (kw < F_IN) ? W1[kw * H1 + wj_ld] : 0.0f;
        }

#pragma unroll
        for (int kk = 0; kk < KC; kk++) {
            const ulonglong2 wA = *(const ulonglong2*)&wsc[kk * H1 + cg * 8];
            const ulonglong2 wB = *(const ulonglong2*)&wsc[kk * H1 + cg * 8 + 4];
#pragma unroll
            for (int i = 0; i < 6; i++) {
                const float xv = xsc[(rt + 128 * i) * XS_STRIDE + kk];
                const unsigned long long xp = pk2(xv, xv);
                fma2(acc[i][0], xp, wA.x);
                fma2(acc[i][1], xp, wA.y);
                fma2(acc[i][2], xp, wB.x);
                fma2(acc[i][3], xp, wB.y);
            }
        }
        __syncthreads();
        if (kt + 1 < NKT) {
#pragma unroll
            for (int t = 0; t < 24; t++) xsn[(rl + 32 * t) * XS_STRIDE + kk_ld] = r[t];
            wsn[tid] = wr;
        }
        __syncthreads();
    }

#pragma unroll
    for (int i = 0; i < 6; i++) {
        const int row = row0 + rt + 128 * i;
        if (row < N_NODES) {
            const float q = rsqrtf((float)g_deg[row]);   // isq inline
            float v[8];
            upk2(v[0], v[1], acc[i][0]);
            upk2(v[2], v[3], acc[i][1]);
            upk2(v[4], v[5], acc[i][2]);
            upk2(v[6], v[7], acc[i][3]);
            float4 o0 = make_float4(v[0]*q, v[1]*q, v[2]*q, v[3]*q);
            float4 o1 = make_float4(v[4]*q, v[5]*q, v[6]*q, v[7]*q);
            g_h1s [row * (H1/4) + 2*cg    ] = o0;
            g_h1s [row * (H1/4) + 2*cg + 1] = o1;
            g_agg1[row * (H1/4) + 2*cg    ] = o0;   // self-loop term
            g_agg1[row * (H1/4) + 2*cg + 1] = o1;
        }
    }
}

// ---------------- vectorized global float4 reduction ----------------
__device__ __forceinline__ void red_add_v4(float4* p, float4 v) {
    asm volatile("red.global.add.v4.f32 [%0], {%1,%2,%3,%4};"
                 :: "l"(p), "f"(v.x), "f"(v.y), "f"(v.z), "f"(v.w) : "memory");
}

// ---------------- K4: scatter layer 1 (8 threads / edge) ----------------
__global__ void k_scatter1() {
    const int tid = blockIdx.x * blockDim.x + threadIdx.x;
    const int e = tid >> 3;
    const int q = tid & 7;
    if (e < NEDGE) {
        const int s = g_src[e];
        const int d = g_dst[e];
        const float4 v = g_h1s[s * (H1/4) + q];
        red_add_v4(&g_agg1[d * (H1/4) + q], v);
    }
}

// ---------------- K5: a1 = relu(isq*agg1 + b1); h2s = isq*(a1@W2) ----------
__global__ void k_layer2(const float* __restrict__ W2, const float* __restrict__ b1) {
    __shared__ float W2s[H1 * H2];
    __shared__ float b1s[H1];
    for (int i = threadIdx.x; i < H1 * H2; i += blockDim.x) W2s[i] = W2[i];
    if (threadIdx.x < H1) b1s[threadIdx.x] = b1[threadIdx.x];
    __syncthreads();

    const int node = blockIdx.x * blockDim.x + threadIdx.x;
    if (node >= N_NODES) return;
    const float q = g_isq[node];

    float a[H1];
#pragma unroll
    for (int k4 = 0; k4 < H1 / 4; k4++) {
        const float4 v = g_agg1[node * (H1/4) + k4];
        a[k4*4+0] = fmaxf(v.x * q + b1s[k4*4+0], 0.0f);
        a[k4*4+1] = fmaxf(v.y * q + b1s[k4*4+1], 0.0f);
        a[k4*4+2] = fmaxf(v.z * q + b1s[k4*4+2], 0.0f);
        a[k4*4+3] = fmaxf(v.w * q + b1s[k4*4+3], 0.0f);
    }
    float acc[H2];
#pragma unroll
    for (int j = 0; j < H2; j++) acc[j] = 0.0f;
#pragma unroll
    for (int k = 0; k < H1; k++) {
        const float ak = a[k];
#pragma unroll
        for (int j4 = 0; j4 < H2 / 4; j4++) {
            const float4 w = *(const float4*)&W2s[k * H2 + j4 * 4];
            acc[j4*4+0] += ak * w.x;
            acc[j4*4+1] += ak * w.y;
            acc[j4*4+2] += ak * w.z;
            acc[j4*4+3] += ak * w.w;
        }
    }
#pragma unroll
    for (int j4 = 0; j4 < H2 / 4; j4++) {
        float4 o = make_float4(acc[j4*4+0]*q, acc[j4*4+1]*q, acc[j4*4+2]*q, acc[j4*4+3]*q);
        g_h2s [node * (H2/4) + j4] = o;
        g_agg2[node * (H2/4) + j4] = o;
    }
}

// ---------------- K6: scatter layer 2 (4 threads / edge) ----------------
__global__ void k_scatter2() {
    const int tid = blockIdx.x * blockDim.x + threadIdx.x;
    const int e = tid >> 2;
    const int q = tid & 3;
    if (e < NEDGE) {
        const int s = g_src[e];
        const int d = g_dst[e];
        const float4 v = g_h2s[s * (H2/4) + q];
        red_add_v4(&g_agg2[d * (H2/4) + q], v);
    }
}

// ---------------- K7: out = log_softmax(relu(isq*agg2+b2) @ Wl + bl) -------
// 512 threads, 4 nodes/iter, z packed {n0,n1}/{n2,n3} as f32x2 -> each Wls
// LDS feeds 4 FMAs via 2 FFMA2.
#define SMEM7_FLOATS (H2 * F_IN + F_IN + H2 + 4 * H2 + 128)
__global__ void __launch_bounds__(512, 1)
k_final(const float* __restrict__ Wl, const float* __restrict__ bl,
        const float* __restrict__ b2, float* __restrict__ out) {
    extern __shared__ float sm[];
    float* Wls = sm;                    // [16][1433]
    float* bls = sm + H2 * F_IN;        // [1433]
    float* b2s = bls + F_IN;            // [16]
    float* a2s = b2s + H2;              // [4][16]
    float* red = a2s + 4 * H2;          // [128]: 64 max + 64 sum partials

    for (int i = threadIdx.x; i < H2 * F_IN; i += 512) Wls[i] = Wl[i];
    for (int i = threadIdx.x; i < F_IN; i += 512)      bls[i] = bl[i];
    if (threadIdx.x < H2)                              b2s[threadIdx.x] = b2[threadIdx.x];
    __syncthreads();

    const int lane = threadIdx.x & 31;
    const int warp = threadIdx.x >> 5;  // 0..15
    const float* agg2f = (const float*)g_agg2;

    for (int base = blockIdx.x * 4; base < N_NODES; base += gridDim.x * 4) {
        if (threadIdx.x < 4 * H2) {
            const int nn   = threadIdx.x >> 4;
            const int k    = threadIdx.x & 15;
            const int node = base + nn;
            float v = 0.0f;
            if (node < N_NODES) {
                const float q = g_isq[node];
                v = fmaxf(q * agg2f[node * H2 + k] + b2s[k], 0.0f);
            }
            a2s[threadIdx.x] = v;
        }
        __syncthreads();

        unsigned long long az01[H2], az23[H2];
#pragma unroll
        for (int k = 0; k < H2; k++) {
            az01[k] = pk2(a2s[k],          a2s[H2 + k]);
            az23[k] = pk2(a2s[2*H2 + k],   a2s[3*H2 + k]);
        }

        unsigned long long z01[3], z23[3];
        float mx0 = -1e30f, mx1 = -1e30f, mx2 = -1e30f, mx3 = -1e30f;
#pragma unroll
        for (int t = 0; t < 3; t++) {
            const int c = threadIdx.x + t * 512;
            if (c < F_IN) {
                const float b = bls[c];
                unsigned long long zb = pk2(b, b);
                unsigned long long s01 = zb, s23 = zb;
#pragma unroll
                for (int k = 0; k < H2; k++) {
                    const float w = Wls[k * F_IN + c];
                    const unsigned long long wp = pk2(w, w);
                    fma2(s01, az01[k], wp);
                    fma2(s23, az23[k], wp);
                }
                z01[t] = s01; z23[t] = s23;
                float f0, f1, f2, f3;
                upk2(f0, f1, s01); upk2(f2, f3, s23);
                mx0 = fmaxf(mx0, f0); mx1 = fmaxf(mx1, f1);
                mx2 = fmaxf(mx2, f2); mx3 = fmaxf(mx3, f3);
            } else {
                z01[t] = pk2(-1e30f, -1e30f);
                z23[t] = pk2(-1e30f, -1e30f);
            }
        }
#pragma unroll
        for (int o = 16; o > 0; o >>= 1) {
            mx0 = fmaxf(mx0, __shfl_xor_sync(0xffffffffu, mx0, o));
            mx1 = fmaxf(mx1, __shfl_xor_sync(0xffffffffu, mx1, o));
            mx2 = fmaxf(mx2, __shfl_xor_sync(0xffffffffu, mx2, o));
            mx3 = fmaxf(mx3, __shfl_xor_sync(0xffffffffu, mx3, o));
        }
        if (lane == 0) {
            red[warp] = mx0; red[16 + warp] = mx1;
            red[32 + warp] = mx2; red[48 + warp] = mx3;
        }
        __syncthreads();
        float bm0 = red[0], bm1 = red[16], bm2 = red[32], bm3 = red[48];
#pragma unroll
        for (int w = 1; w < 16; w++) {
            bm0 = fmaxf(bm0, red[w]);       bm1 = fmaxf(bm1, red[16 + w]);
            bm2 = fmaxf(bm2, red[32 + w]);  bm3 = fmaxf(bm3, red[48 + w]);
        }

        float se0 = 0.f, se1 = 0.f, se2 = 0.f, se3 = 0.f;
#pragma unroll
        for (int t = 0; t < 3; t++) {
            const int c = threadIdx.x + t * 512;
            if (c < F_IN) {
                float f0, f1, f2, f3;
                upk2(f0, f1, z01[t]); upk2(f2, f3, z23[t]);
                se0 += __expf(f0 - bm0); se1 += __expf(f1 - bm1);
                se2 += __expf(f2 - bm2); se3 += __expf(f3 - bm3);
            }
        }
#pragma unroll
        for (int o = 16; o > 0; o >>= 1) {
            se0 += __shfl_xor_sync(0xffffffffu, se0, o);
            se1 += __shfl_xor_sync(0xffffffffu, se1, o);
            se2 += __shfl_xor_sync(0xffffffffu, se2, o);
            se3 += __shfl_xor_sync(0xffffffffu, se3, o);
        }
        if (lane == 0) {
            red[64 + warp] = se0; red[80 + warp] = se1;
            red[96 + warp] = se2; red[112 + warp] = se3;
        }
        __syncthreads();
        float s0 = 0.f, s1 = 0.f, s2 = 0.f, s3 = 0.f;
#pragma unroll
        for (int w = 0; w < 16; w++) {
            s0 += red[64 + w];  s1 += red[80 + w];
            s2 += red[96 + w];  s3 += red[112 + w];
        }
        const float lse0 = bm0 + __logf(s0);
        const float lse1 = bm1 + __logf(s1);
        const float lse2 = bm2 + __logf(s2);
        const float lse3 = bm3 + __logf(s3);

#pragma unroll
        for (int t = 0; t < 3; t++) {
            const int c = threadIdx.x + t * 512;
            if (c < F_IN) {
                float f0, f1, f2, f3;
                upk2(f0, f1, z01[t]); upk2(f2, f3, z23[t]);
                if (base     < N_NODES) out[(size_t)(base    ) * F_IN + c] = f0 - lse0;
                if (base + 1 < N_NODES) out[(size_t)(base + 1) * F_IN + c] = f1 - lse1;
                if (base + 2 < N_NODES) out[(size_t)(base + 2) * F_IN + c] = f2 - lse2;
                if (base + 3 < N_NODES) out[(size_t)(base + 3) * F_IN + c] = f3 - lse3;
            }
        }
        __syncthreads();   // protect a2s / red for next iteration
    }
}

// ---------------- launcher ----------------
extern "C" void kernel_launch(void* const* d_in, const int* in_sizes, int n_in,
                              void* d_out, int out_size) {
    const float* x   = (const float*)d_in[0];
    const float* W1  = (const float*)d_in[1];
    const float* b1  = (const float*)d_in[2];
    const float* W2  = (const float*)d_in[3];
    const float* b2  = (const float*)d_in[4];
    const float* Wl  = (const float*)d_in[5];
    const float* bl  = (const float*)d_in[6];
    const int*   ei32 = (const int*)d_in[7];
    float* out = (float*)d_out;
    (void)in_sizes; (void)n_in; (void)out_size;

    const int smem1 = SMEM1_FLOATS * (int)sizeof(float);   // ~106 KB
    const int smem7 = SMEM7_FLOATS * (int)sizeof(float);   // ~98 KB
    cudaFuncSetAttribute(k_gemm1, cudaFuncAttributeMaxDynamicSharedMemorySize, smem1);
    cudaFuncSetAttribute(k_final, cudaFuncAttributeMaxDynamicSharedMemorySize, smem7);

    k_deg_init<<<(N_NODES + 255) / 256, 256>>>();
    k_detect  <<<(NEDGE   + 255) / 256, 256>>>(ei32);
    k_edge    <<<(NEDGE   + 255) / 256, 256>>>(ei32);

    k_gemm1   <<<(N_NODES + RB - 1) / RB, 512, smem1>>>(x, W1);   // launch idx 3
    k_isq     <<<(N_NODES + 255) / 256, 256>>>();
    k_scatter1<<<(NEDGE * 8 + 255) / 256, 256>>>();
    k_layer2  <<<(N_NODES + 127) / 128, 128>>>(W2, b1);
    k_scatter2<<<(NEDGE * 4 + 255) / 256, 256>>>();
    k_final   <<<148, 512, smem7>>>(Wl, bl, b2, out);
}